// round 1
// baseline (speedup 1.0000x reference)
#include <cuda_runtime.h>
#include <math.h>

#define D_EMBED 2048
#define NHEAD   8
#define HDIM    256
#define BATCH   32
#define SEQ     256
#define ROWS    (BATCH*SEQ)   /* 8192 */
#define DFF     (4*D_EMBED)   /* 8192 */

// ---------------- scratch (device globals; no runtime allocation) -------------
__device__ float g_h [ROWS*D_EMBED];
__device__ float g_q [ROWS*D_EMBED];
__device__ float g_k [ROWS*D_EMBED];
__device__ float g_v [ROWS*D_EMBED];
__device__ float g_s [BATCH*NHEAD*SEQ*SEQ];
__device__ float g_ao[ROWS*D_EMBED];
__device__ float g_x1[ROWS*D_EMBED];
__device__ float g_h2[ROWS*D_EMBED];
__device__ float g_m1[ROWS*DFF];

// ---------------- layernorm ---------------------------------------------------
__global__ void __launch_bounds__(256) ln_kernel(const float* __restrict__ x,
                                                 const float* __restrict__ g,
                                                 const float* __restrict__ b,
                                                 float* __restrict__ out)
{
    __shared__ float red[256];
    const int row = blockIdx.x;
    const float* xr = x + (size_t)row * D_EMBED;
    float* orow = out + (size_t)row * D_EMBED;
    const int tid = threadIdx.x;

    float v[8];
    float s = 0.f;
#pragma unroll
    for (int i = 0; i < 8; i++) { v[i] = xr[tid + 256*i]; s += v[i]; }
    red[tid] = s; __syncthreads();
#pragma unroll
    for (int o = 128; o > 0; o >>= 1) { if (tid < o) red[tid] += red[tid+o]; __syncthreads(); }
    const float mean = red[0] * (1.0f / D_EMBED);
    __syncthreads();

    float q = 0.f;
#pragma unroll
    for (int i = 0; i < 8; i++) { float d = v[i] - mean; q += d*d; }
    red[tid] = q; __syncthreads();
#pragma unroll
    for (int o = 128; o > 0; o >>= 1) { if (tid < o) red[tid] += red[tid+o]; __syncthreads(); }
    const float rstd = rsqrtf(red[0] * (1.0f / D_EMBED) + 1e-5f);

#pragma unroll
    for (int i = 0; i < 8; i++) {
        const int c = tid + 256*i;
        orow[c] = (v[i] - mean) * rstd * g[c] + b[c];
    }
}

// ---------------- causal softmax over rows of length SEQ ----------------------
__global__ void __launch_bounds__(256) softmax_kernel(float* __restrict__ s)
{
    __shared__ float red[256];
    const int row = blockIdx.x;           // b*H*T + h*T + t
    const int t = row & (SEQ - 1);
    float* sr = s + (size_t)row * SEQ;
    const int tid = threadIdx.x;

    const float val = (tid <= t) ? sr[tid] : -INFINITY;
    red[tid] = val; __syncthreads();
#pragma unroll
    for (int o = 128; o > 0; o >>= 1) { if (tid < o) red[tid] = fmaxf(red[tid], red[tid+o]); __syncthreads(); }
    const float mx = red[0];
    __syncthreads();

    const float e = (tid <= t) ? expf(val - mx) : 0.f;
    red[tid] = e; __syncthreads();
#pragma unroll
    for (int o = 128; o > 0; o >>= 1) { if (tid < o) red[tid] += red[tid+o]; __syncthreads(); }
    sr[tid] = e / red[0];
}

// ---------------- generic SGEMM 128x128x8, 8x8/thread, double buffered --------
#define GBM 128
#define GBN 128
#define GBK 8
#define EP_BIAS 1
#define EP_GELU 2
#define EP_RES  4

__global__ void __launch_bounds__(256) gemm_kernel(
    const float* __restrict__ A, const float* __restrict__ B,
    const float* __restrict__ bias, const float* __restrict__ Rs,
    float* __restrict__ C,
    int K, int lda, int ldb, int ldc,
    int innerCnt, long aO, long aI, long bO, long bI, long cO, long cI,
    float alpha, int transB, int mode, int causal)
{
    __shared__ __align__(16) float As[2][GBK][GBM];
    __shared__ __align__(16) float Bs[2][GBK][GBN];

    const int z  = blockIdx.z;
    const int zo = z / innerCnt;
    const int zi = z - zo * innerCnt;
    const float* Ab = A + (size_t)zo * aO + (size_t)zi * aI;
    const float* Bb = B + (size_t)zo * bO + (size_t)zi * bI;
    float*       Cb = C + (size_t)zo * cO + (size_t)zi * cI;
    const float* Rb = Rs ? Rs + (size_t)zo * cO + (size_t)zi * cI : nullptr;

    const int bm = blockIdx.y * GBM;
    const int bn = blockIdx.x * GBN;
    if (causal && bn > bm) return;      // tile entirely above the diagonal

    const int tid  = threadIdx.x;
    const int arow = tid >> 1;          // 0..127
    const int acol = (tid & 1) << 2;    // 0 or 4
    const int brow = tid >> 5;          // 0..7
    const int bcol = (tid & 31) << 2;   // 0..124

    const float* Aptr = Ab + (size_t)(bm + arow) * lda + acol;
    const float* Bptr = transB ? (Bb + (size_t)(bn + arow) * ldb + acol)
                               : (Bb + (size_t)brow * ldb + bn + bcol);

    // prologue: load k-tile 0
    {
        const float4 a4 = *(const float4*)Aptr;
        As[0][acol+0][arow] = a4.x;
        As[0][acol+1][arow] = a4.y;
        As[0][acol+2][arow] = a4.z;
        As[0][acol+3][arow] = a4.w;
        if (!transB) {
            *(float4*)&Bs[0][brow][bcol] = *(const float4*)Bptr;
        } else {
            const float4 b4 = *(const float4*)Bptr;
            Bs[0][acol+0][arow] = b4.x;
            Bs[0][acol+1][arow] = b4.y;
            Bs[0][acol+2][arow] = b4.z;
            Bs[0][acol+3][arow] = b4.w;
        }
    }
    __syncthreads();

    float acc[8][8];
#pragma unroll
    for (int i = 0; i < 8; i++)
#pragma unroll
        for (int j = 0; j < 8; j++) acc[i][j] = 0.f;

    const int trow = (tid >> 4) * 4;    // 0..60
    const int tcol = (tid & 15) * 4;    // 0..60

    int buf = 0;
    for (int k0 = GBK; k0 <= K; k0 += GBK) {
        const bool more = (k0 < K);
        float4 na, nb;
        if (more) {
            na = *(const float4*)(Aptr + k0);
            nb = transB ? *(const float4*)(Bptr + k0)
                        : *(const float4*)(Bptr + (size_t)k0 * ldb);
        }

#pragma unroll
        for (int kk = 0; kk < GBK; kk++) {
            const float4 a0 = *(const float4*)&As[buf][kk][trow];
            const float4 a1 = *(const float4*)&As[buf][kk][trow + 64];
            const float4 b0 = *(const float4*)&Bs[buf][kk][tcol];
            const float4 b1 = *(const float4*)&Bs[buf][kk][tcol + 64];
            const float ar[8] = {a0.x,a0.y,a0.z,a0.w,a1.x,a1.y,a1.z,a1.w};
            const float br[8] = {b0.x,b0.y,b0.z,b0.w,b1.x,b1.y,b1.z,b1.w};
#pragma unroll
            for (int i = 0; i < 8; i++)
#pragma unroll
                for (int j = 0; j < 8; j++)
                    acc[i][j] += ar[i] * br[j];
        }

        if (more) {
            buf ^= 1;
            As[buf][acol+0][arow] = na.x;
            As[buf][acol+1][arow] = na.y;
            As[buf][acol+2][arow] = na.z;
            As[buf][acol+3][arow] = na.w;
            if (!transB) {
                *(float4*)&Bs[buf][brow][bcol] = nb;
            } else {
                Bs[buf][acol+0][arow] = nb.x;
                Bs[buf][acol+1][arow] = nb.y;
                Bs[buf][acol+2][arow] = nb.z;
                Bs[buf][acol+3][arow] = nb.w;
            }
            __syncthreads();
        }
    }

    // epilogue
#pragma unroll
    for (int ih = 0; ih < 2; ih++) {
#pragma unroll
        for (int i = 0; i < 4; i++) {
            const int r = bm + trow + ih*64 + i;
            float* crow = Cb + (size_t)r * ldc + bn;
#pragma unroll
            for (int jh = 0; jh < 2; jh++) {
                const int c = tcol + jh*64;
                float o0 = alpha * acc[ih*4+i][jh*4+0];
                float o1 = alpha * acc[ih*4+i][jh*4+1];
                float o2 = alpha * acc[ih*4+i][jh*4+2];
                float o3 = alpha * acc[ih*4+i][jh*4+3];
                if (mode & EP_BIAS) {
                    const float4 bb = *(const float4*)(bias + bn + c);
                    o0 += bb.x; o1 += bb.y; o2 += bb.z; o3 += bb.w;
                }
                if (mode & EP_GELU) {
                    o0 *= normcdff(o0); o1 *= normcdff(o1);
                    o2 *= normcdff(o2); o3 *= normcdff(o3);
                }
                if (mode & EP_RES) {
                    const float4 rv = *(const float4*)(Rb + (size_t)r * ldc + bn + c);
                    o0 += rv.x; o1 += rv.y; o2 += rv.z; o3 += rv.w;
                }
                float4 vv; vv.x = o0; vv.y = o1; vv.z = o2; vv.w = o3;
                *(float4*)(crow + c) = vv;
            }
        }
    }
}

// ---------------- host-side launch helper -------------------------------------
static void gemm(const float* A, const float* B, const float* bias, const float* res,
                 float* C, int M, int N, int K, int lda, int ldb, int ldc, int mode,
                 float alpha = 1.f, int transB = 0, int causal = 0,
                 int batch = 1, int innerCnt = 1,
                 long aO = 0, long aI = 0, long bO = 0, long bI = 0,
                 long cO = 0, long cI = 0)
{
    dim3 grid(N / GBN, M / GBM, batch);
    gemm_kernel<<<grid, 256>>>(A, B, bias, res, C, K, lda, ldb, ldc,
                               innerCnt, aO, aI, bO, bI, cO, cI,
                               alpha, transB, mode, causal);
}

extern "C" void kernel_launch(void* const* d_in, const int* in_sizes, int n_in,
                              void* d_out, int out_size)
{
    const float* x    = (const float*)d_in[0];
    const float* ln1g = (const float*)d_in[1];
    const float* ln1b = (const float*)d_in[2];
    const float* wq   = (const float*)d_in[3];
    const float* bq   = (const float*)d_in[4];
    const float* wk   = (const float*)d_in[5];
    const float* bk   = (const float*)d_in[6];
    const float* wv   = (const float*)d_in[7];
    const float* bv   = (const float*)d_in[8];
    const float* wo   = (const float*)d_in[9];
    const float* bo   = (const float*)d_in[10];
    const float* ln2g = (const float*)d_in[11];
    const float* ln2b = (const float*)d_in[12];
    const float* w1   = (const float*)d_in[13];
    const float* b1   = (const float*)d_in[14];
    const float* w2   = (const float*)d_in[15];
    const float* b2   = (const float*)d_in[16];
    float* out = (float*)d_out;

    float *h, *q, *k, *v, *s, *ao, *x1, *h2, *m1;
    cudaGetSymbolAddress((void**)&h,  g_h);
    cudaGetSymbolAddress((void**)&q,  g_q);
    cudaGetSymbolAddress((void**)&k,  g_k);
    cudaGetSymbolAddress((void**)&v,  g_v);
    cudaGetSymbolAddress((void**)&s,  g_s);
    cudaGetSymbolAddress((void**)&ao, g_ao);
    cudaGetSymbolAddress((void**)&x1, g_x1);
    cudaGetSymbolAddress((void**)&h2, g_h2);
    cudaGetSymbolAddress((void**)&m1, g_m1);

    // 1. h = LN1(x)
    ln_kernel<<<ROWS, 256>>>(x, ln1g, ln1b, h);

    // 2. Q, K, V projections
    gemm(h, wq, bq, nullptr, q, ROWS, D_EMBED, D_EMBED, D_EMBED, D_EMBED, D_EMBED, EP_BIAS);
    gemm(h, wk, bk, nullptr, k, ROWS, D_EMBED, D_EMBED, D_EMBED, D_EMBED, D_EMBED, EP_BIAS);
    gemm(h, wv, bv, nullptr, v, ROWS, D_EMBED, D_EMBED, D_EMBED, D_EMBED, D_EMBED, EP_BIAS);

    // 3. scores[b,h] = (1/16) * Q[b,:,h,:] @ K[b,:,h,:]^T   (causal tiles skipped)
    //    batch z = b*8 + h  ->  zo = b, zi = h (innerCnt = 8)
    gemm(q, k, nullptr, nullptr, s,
         SEQ, SEQ, HDIM, D_EMBED, D_EMBED, SEQ, 0 /*raw*/,
         0.0625f, /*transB=*/1, /*causal=*/1,
         BATCH * NHEAD, NHEAD,
         (long)SEQ * D_EMBED, (long)HDIM,          // A: b stride, h stride
         (long)SEQ * D_EMBED, (long)HDIM,          // B (= K): same
         (long)NHEAD * SEQ * SEQ, (long)SEQ * SEQ);// C: scores [bh][T][T]

    // 4. causal softmax in-place
    softmax_kernel<<<BATCH * NHEAD * SEQ, 256>>>(s);

    // 5. ao[b,:,h,:] = att[b,h] @ V[b,:,h,:]
    gemm(s, v, nullptr, nullptr, ao,
         SEQ, HDIM, SEQ, SEQ, D_EMBED, D_EMBED, 0 /*raw*/,
         1.0f, 0, 0,
         BATCH * NHEAD, NHEAD,
         (long)NHEAD * SEQ * SEQ, (long)SEQ * SEQ, // A: scores
         (long)SEQ * D_EMBED, (long)HDIM,          // B: v
         (long)SEQ * D_EMBED, (long)HDIM);         // C: ao

    // 6. x1 = x + ao @ Wo + bo
    gemm(ao, wo, bo, x, x1, ROWS, D_EMBED, D_EMBED, D_EMBED, D_EMBED, D_EMBED,
         EP_BIAS | EP_RES);

    // 7. h2 = LN2(x1)
    ln_kernel<<<ROWS, 256>>>(x1, ln2g, ln2b, h2);

    // 8. m1 = gelu(h2 @ W1 + b1)
    gemm(h2, w1, b1, nullptr, m1, ROWS, DFF, D_EMBED, D_EMBED, DFF, DFF,
         EP_BIAS | EP_GELU);

    // 9. out = x1 + m1 @ W2 + b2
    gemm(m1, w2, b2, x1, out, ROWS, D_EMBED, DFF, DFF, D_EMBED, D_EMBED,
         EP_BIAS | EP_RES);
}

// round 2
// speedup vs baseline: 1.2049x; 1.2049x over previous
#include <cuda_runtime.h>
#include <math.h>
#include <stdint.h>

#define D_EMBED 2048
#define NHEAD   8
#define HDIM    256
#define BATCH   32
#define SEQ     256
#define ROWS    (BATCH*SEQ)   /* 8192 */
#define DFF     (4*D_EMBED)   /* 8192 */

// ---------------- scratch (device globals; no runtime allocation) -------------
__device__ float g_h [ROWS*D_EMBED];
__device__ float g_q [ROWS*D_EMBED];
__device__ float g_k [ROWS*D_EMBED];
__device__ float g_v [ROWS*D_EMBED];
__device__ float g_s [BATCH*NHEAD*SEQ*SEQ];
__device__ float g_ao[ROWS*D_EMBED];
__device__ float g_x1[ROWS*D_EMBED];
__device__ float g_h2[ROWS*D_EMBED];
__device__ float g_m1[ROWS*DFF];

// ---------------- layernorm ---------------------------------------------------
__global__ void __launch_bounds__(256) ln_kernel(const float* __restrict__ x,
                                                 const float* __restrict__ g,
                                                 const float* __restrict__ b,
                                                 float* __restrict__ out)
{
    __shared__ float red[256];
    const int row = blockIdx.x;
    const float* xr = x + (size_t)row * D_EMBED;
    float* orow = out + (size_t)row * D_EMBED;
    const int tid = threadIdx.x;

    float v[8];
    float s = 0.f;
#pragma unroll
    for (int i = 0; i < 8; i++) { v[i] = xr[tid + 256*i]; s += v[i]; }
    red[tid] = s; __syncthreads();
#pragma unroll
    for (int o = 128; o > 0; o >>= 1) { if (tid < o) red[tid] += red[tid+o]; __syncthreads(); }
    const float mean = red[0] * (1.0f / D_EMBED);
    __syncthreads();

    float q = 0.f;
#pragma unroll
    for (int i = 0; i < 8; i++) { float d = v[i] - mean; q += d*d; }
    red[tid] = q; __syncthreads();
#pragma unroll
    for (int o = 128; o > 0; o >>= 1) { if (tid < o) red[tid] += red[tid+o]; __syncthreads(); }
    const float rstd = rsqrtf(red[0] * (1.0f / D_EMBED) + 1e-5f);

#pragma unroll
    for (int i = 0; i < 8; i++) {
        const int c = tid + 256*i;
        orow[c] = (v[i] - mean) * rstd * g[c] + b[c];
    }
}

// ---------------- causal softmax over rows of length SEQ ----------------------
__global__ void __launch_bounds__(256) softmax_kernel(float* __restrict__ s)
{
    __shared__ float red[256];
    const int row = blockIdx.x;           // b*H*T + h*T + t
    const int t = row & (SEQ - 1);
    float* sr = s + (size_t)row * SEQ;
    const int tid = threadIdx.x;

    const float val = (tid <= t) ? sr[tid] : -INFINITY;
    red[tid] = val; __syncthreads();
#pragma unroll
    for (int o = 128; o > 0; o >>= 1) { if (tid < o) red[tid] = fmaxf(red[tid], red[tid+o]); __syncthreads(); }
    const float mx = red[0];
    __syncthreads();

    const float e = (tid <= t) ? expf(val - mx) : 0.f;
    red[tid] = e; __syncthreads();
#pragma unroll
    for (int o = 128; o > 0; o >>= 1) { if (tid < o) red[tid] += red[tid+o]; __syncthreads(); }
    sr[tid] = e / red[0];
}

// ---------------- tf32x3 tensor-core GEMM -------------------------------------
// Block tile 128x128, BK=16, 256 threads = 8 warps (2 M x 4 N), warp tile 64x32.
// a = a_hi + a_lo (tf32 split); D += Ahi*Bhi + Ahi*Blo + Alo*Bhi  -> ~fp32 accuracy.

#define EP_BIAS 1
#define EP_GELU 2
#define EP_RES  4

#define ASTRIDE 20    /* padded floats per A smem row [m][k]  (conflict-free frags) */
#define BSTRIDE 136   /* padded floats per B smem row [k][n]  (conflict-free frags) */

__device__ __forceinline__ uint32_t f2tf32(float f) {
    uint32_t r; asm("cvt.rna.tf32.f32 %0, %1;" : "=r"(r) : "f"(f)); return r;
}

__device__ __forceinline__ void mma8(float c[4],
                                     uint32_t a0, uint32_t a1, uint32_t a2, uint32_t a3,
                                     uint32_t b0, uint32_t b1)
{
    asm volatile(
        "mma.sync.aligned.m16n8k8.row.col.f32.tf32.tf32.f32 "
        "{%0,%1,%2,%3}, {%4,%5,%6,%7}, {%8,%9}, {%0,%1,%2,%3};\n"
        : "+f"(c[0]), "+f"(c[1]), "+f"(c[2]), "+f"(c[3])
        : "r"(a0), "r"(a1), "r"(a2), "r"(a3), "r"(b0), "r"(b1));
}

template<int TRANSB>
__global__ void __launch_bounds__(256, 1) gemm_tc(
    const float* __restrict__ A, const float* __restrict__ B,
    const float* __restrict__ bias, const float* __restrict__ Rs,
    float* __restrict__ C,
    int K, int lda, int ldb, int ldc,
    int innerCnt, long aO, long aI, long bO, long bI, long cO, long cI,
    float alpha, int mode, int causal)
{
    __shared__ __align__(16) float As[2][128 * ASTRIDE];
    __shared__ __align__(16) float Bs[2][TRANSB ? (128 * ASTRIDE) : (16 * BSTRIDE)];

    const int z  = blockIdx.z;
    const int zo = z / innerCnt;
    const int zi = z - zo * innerCnt;
    const float* Ab = A + (size_t)zo * aO + (size_t)zi * aI;
    const float* Bb = B + (size_t)zo * bO + (size_t)zi * bI;
    float*       Cb = C + (size_t)zo * cO + (size_t)zi * cI;
    const float* Rb = Rs ? Rs + (size_t)zo * cO + (size_t)zi * cI : nullptr;

    const int bm = blockIdx.y * 128;
    const int bn = blockIdx.x * 128;
    if (causal && bn > bm) return;

    const int tid  = threadIdx.x;
    const int lane = tid & 31;
    const int wid  = tid >> 5;
    const int wm   = (wid >> 2) * 64;   // warp M offset: 0 or 64
    const int wn   = (wid & 3) * 32;    // warp N offset: 0,32,64,96
    const int lr   = lane >> 2;         // group id 0..7
    const int lc   = lane & 3;          // thread-in-group 0..3

    // ---- gmem staging addresses ----
    const int ar = tid >> 1;            // A tile row 0..127
    const int ac = (tid & 1) * 8;       // A k offset 0 or 8
    const float* Ag = Ab + (size_t)(bm + ar) * lda + ac;

    const float* Bg;
    if (TRANSB) {
        Bg = Bb + (size_t)(bn + ar) * ldb + ac;          // [n][k] rows
    } else {
        const int bkr = tid >> 4;        // 0..15 (k)
        const int bnc = (tid & 15) * 8;  // 0..120 (n)
        Bg = Bb + (size_t)bkr * ldb + bn + bnc;
    }
    const int b_sts = TRANSB ? (ar * ASTRIDE + ac)
                             : ((tid >> 4) * BSTRIDE + (tid & 15) * 8);
    const int a_sts = ar * ASTRIDE + ac;

    // ---- accumulators ----
    float acc[4][4][4];
#pragma unroll
    for (int i = 0; i < 4; i++)
#pragma unroll
        for (int j = 0; j < 4; j++)
#pragma unroll
            for (int t = 0; t < 4; t++) acc[i][j][t] = 0.f;

    // ---- prologue: tile 0 -> smem[0] ----
    {
        float4 a0 = *(const float4*)(Ag);
        float4 a1 = *(const float4*)(Ag + 4);
        *(float4*)&As[0][a_sts]     = a0;
        *(float4*)&As[0][a_sts + 4] = a1;
        float4 b0, b1;
        if (TRANSB) { b0 = *(const float4*)(Bg); b1 = *(const float4*)(Bg + 4); }
        else        { b0 = *(const float4*)(Bg); b1 = *(const float4*)(Bg + 4); }
        *(float4*)&Bs[0][b_sts]     = b0;
        *(float4*)&Bs[0][b_sts + 4] = b1;
    }
    __syncthreads();

    const int KT = K >> 4;   // K/16 tiles
    for (int kt = 0; kt < KT; kt++) {
        const int buf = kt & 1;
        const bool more = (kt + 1 < KT);

        float4 na0, na1, nb0, nb1;
        if (more) {
            const float* Agn = Ag + (kt + 1) * 16;
            na0 = *(const float4*)(Agn);
            na1 = *(const float4*)(Agn + 4);
            if (TRANSB) {
                const float* Bgn = Bg + (kt + 1) * 16;
                nb0 = *(const float4*)(Bgn);
                nb1 = *(const float4*)(Bgn + 4);
            } else {
                const float* Bgn = Bg + (size_t)(kt + 1) * 16 * ldb;
                nb0 = *(const float4*)(Bgn);
                nb1 = *(const float4*)(Bgn + 4);
            }
        }

        // ---- compute this tile: 2 k8 steps ----
#pragma unroll
        for (int ks = 0; ks < 2; ks++) {
            const int koff = ks * 8;

            uint32_t aH[4][4], aL[4][4];
#pragma unroll
            for (int mt = 0; mt < 4; mt++) {
                const float* ap = &As[buf][(wm + mt * 16 + lr) * ASTRIDE + koff + lc];
                float f0 = ap[0];
                float f1 = ap[8 * ASTRIDE];
                float f2 = ap[4];
                float f3 = ap[8 * ASTRIDE + 4];
                aH[mt][0] = f2tf32(f0); aL[mt][0] = f2tf32(f0 - __uint_as_float(aH[mt][0]));
                aH[mt][1] = f2tf32(f1); aL[mt][1] = f2tf32(f1 - __uint_as_float(aH[mt][1]));
                aH[mt][2] = f2tf32(f2); aL[mt][2] = f2tf32(f2 - __uint_as_float(aH[mt][2]));
                aH[mt][3] = f2tf32(f3); aL[mt][3] = f2tf32(f3 - __uint_as_float(aH[mt][3]));
            }

            uint32_t bH[4][2], bL[4][2];
#pragma unroll
            for (int nt = 0; nt < 4; nt++) {
                float g0, g1;
                if (TRANSB) {
                    const float* bp = &Bs[buf][(wn + nt * 8 + lr) * ASTRIDE + koff + lc];
                    g0 = bp[0];
                    g1 = bp[4];
                } else {
                    const float* bp = &Bs[buf][(koff + lc) * BSTRIDE + wn + nt * 8 + lr];
                    g0 = bp[0];
                    g1 = bp[4 * BSTRIDE];
                }
                bH[nt][0] = f2tf32(g0); bL[nt][0] = f2tf32(g0 - __uint_as_float(bH[nt][0]));
                bH[nt][1] = f2tf32(g1); bL[nt][1] = f2tf32(g1 - __uint_as_float(bH[nt][1]));
            }

#pragma unroll
            for (int mt = 0; mt < 4; mt++) {
#pragma unroll
                for (int nt = 0; nt < 4; nt++) {
                    mma8(acc[mt][nt], aH[mt][0], aH[mt][1], aH[mt][2], aH[mt][3],
                         bH[nt][0], bH[nt][1]);
                    mma8(acc[mt][nt], aH[mt][0], aH[mt][1], aH[mt][2], aH[mt][3],
                         bL[nt][0], bL[nt][1]);
                    mma8(acc[mt][nt], aL[mt][0], aL[mt][1], aL[mt][2], aL[mt][3],
                         bH[nt][0], bH[nt][1]);
                }
            }
        }

        if (more) {
            const int nb = buf ^ 1;
            *(float4*)&As[nb][a_sts]     = na0;
            *(float4*)&As[nb][a_sts + 4] = na1;
            *(float4*)&Bs[nb][b_sts]     = nb0;
            *(float4*)&Bs[nb][b_sts + 4] = nb1;
        }
        __syncthreads();
    }

    // ---- epilogue ----
#pragma unroll
    for (int mt = 0; mt < 4; mt++) {
        const int r = bm + wm + mt * 16 + lr;
#pragma unroll
        for (int half = 0; half < 2; half++) {
            const int rr = r + half * 8;
            float* crow = Cb + (size_t)rr * ldc;
            const float* rrow = (mode & EP_RES) ? (Rb + (size_t)rr * ldc) : nullptr;
#pragma unroll
            for (int nt = 0; nt < 4; nt++) {
                const int col = bn + wn + nt * 8 + 2 * lc;
                float o0 = alpha * acc[mt][nt][half * 2 + 0];
                float o1 = alpha * acc[mt][nt][half * 2 + 1];
                if (mode & EP_BIAS) {
                    const float2 bb = *(const float2*)(bias + col);
                    o0 += bb.x; o1 += bb.y;
                }
                if (mode & EP_GELU) {
                    o0 *= normcdff(o0);
                    o1 *= normcdff(o1);
                }
                if (mode & EP_RES) {
                    const float2 rv = *(const float2*)(rrow + col);
                    o0 += rv.x; o1 += rv.y;
                }
                *(float2*)(crow + col) = make_float2(o0, o1);
            }
        }
    }
}

// ---------------- host-side launch helper -------------------------------------
static void gemm(const float* A, const float* B, const float* bias, const float* res,
                 float* C, int M, int N, int K, int lda, int ldb, int ldc, int mode,
                 float alpha = 1.f, int transB = 0, int causal = 0,
                 int batch = 1, int innerCnt = 1,
                 long aO = 0, long aI = 0, long bO = 0, long bI = 0,
                 long cO = 0, long cI = 0)
{
    dim3 grid(N / 128, M / 128, batch);
    if (transB)
        gemm_tc<1><<<grid, 256>>>(A, B, bias, res, C, K, lda, ldb, ldc,
                                  innerCnt, aO, aI, bO, bI, cO, cI,
                                  alpha, mode, causal);
    else
        gemm_tc<0><<<grid, 256>>>(A, B, bias, res, C, K, lda, ldb, ldc,
                                  innerCnt, aO, aI, bO, bI, cO, cI,
                                  alpha, mode, causal);
}

extern "C" void kernel_launch(void* const* d_in, const int* in_sizes, int n_in,
                              void* d_out, int out_size)
{
    const float* x    = (const float*)d_in[0];
    const float* ln1g = (const float*)d_in[1];
    const float* ln1b = (const float*)d_in[2];
    const float* wq   = (const float*)d_in[3];
    const float* bq   = (const float*)d_in[4];
    const float* wk   = (const float*)d_in[5];
    const float* bk   = (const float*)d_in[6];
    const float* wv   = (const float*)d_in[7];
    const float* bv   = (const float*)d_in[8];
    const float* wo   = (const float*)d_in[9];
    const float* bo   = (const float*)d_in[10];
    const float* ln2g = (const float*)d_in[11];
    const float* ln2b = (const float*)d_in[12];
    const float* w1   = (const float*)d_in[13];
    const float* b1   = (const float*)d_in[14];
    const float* w2   = (const float*)d_in[15];
    const float* b2   = (const float*)d_in[16];
    float* out = (float*)d_out;

    float *h, *q, *k, *v, *s, *ao, *x1, *h2, *m1;
    cudaGetSymbolAddress((void**)&h,  g_h);
    cudaGetSymbolAddress((void**)&q,  g_q);
    cudaGetSymbolAddress((void**)&k,  g_k);
    cudaGetSymbolAddress((void**)&v,  g_v);
    cudaGetSymbolAddress((void**)&s,  g_s);
    cudaGetSymbolAddress((void**)&ao, g_ao);
    cudaGetSymbolAddress((void**)&x1, g_x1);
    cudaGetSymbolAddress((void**)&h2, g_h2);
    cudaGetSymbolAddress((void**)&m1, g_m1);

    // 1. h = LN1(x)
    ln_kernel<<<ROWS, 256>>>(x, ln1g, ln1b, h);

    // 2. Q, K, V projections
    gemm(h, wq, bq, nullptr, q, ROWS, D_EMBED, D_EMBED, D_EMBED, D_EMBED, D_EMBED, EP_BIAS);
    gemm(h, wk, bk, nullptr, k, ROWS, D_EMBED, D_EMBED, D_EMBED, D_EMBED, D_EMBED, EP_BIAS);
    gemm(h, wv, bv, nullptr, v, ROWS, D_EMBED, D_EMBED, D_EMBED, D_EMBED, D_EMBED, EP_BIAS);

    // 3. scores[b,h] = (1/16) * Q[b,:,h,:] @ K[b,:,h,:]^T   (causal tiles skipped)
    gemm(q, k, nullptr, nullptr, s,
         SEQ, SEQ, HDIM, D_EMBED, D_EMBED, SEQ, 0 /*raw*/,
         0.0625f, /*transB=*/1, /*causal=*/1,
         BATCH * NHEAD, NHEAD,
         (long)SEQ * D_EMBED, (long)HDIM,
         (long)SEQ * D_EMBED, (long)HDIM,
         (long)NHEAD * SEQ * SEQ, (long)SEQ * SEQ);

    // 4. causal softmax in-place
    softmax_kernel<<<BATCH * NHEAD * SEQ, 256>>>(s);

    // 5. ao[b,:,h,:] = att[b,h] @ V[b,:,h,:]
    gemm(s, v, nullptr, nullptr, ao,
         SEQ, HDIM, SEQ, SEQ, D_EMBED, D_EMBED, 0 /*raw*/,
         1.0f, 0, 0,
         BATCH * NHEAD, NHEAD,
         (long)NHEAD * SEQ * SEQ, (long)SEQ * SEQ,
         (long)SEQ * D_EMBED, (long)HDIM,
         (long)SEQ * D_EMBED, (long)HDIM);

    // 6. x1 = x + ao @ Wo + bo
    gemm(ao, wo, bo, x, x1, ROWS, D_EMBED, D_EMBED, D_EMBED, D_EMBED, D_EMBED,
         EP_BIAS | EP_RES);

    // 7. h2 = LN2(x1)
    ln_kernel<<<ROWS, 256>>>(x1, ln2g, ln2b, h2);

    // 8. m1 = gelu(h2 @ W1 + b1)
    gemm(h2, w1, b1, nullptr, m1, ROWS, DFF, D_EMBED, D_EMBED, DFF, DFF,
         EP_BIAS | EP_GELU);

    // 9. out = x1 + m1 @ W2 + b2
    gemm(m1, w2, b2, x1, out, ROWS, D_EMBED, DFF, DFF, D_EMBED, D_EMBED,
         EP_BIAS | EP_RES);
}

// round 4
// speedup vs baseline: 2.4740x; 2.0534x over previous
#include <cuda_runtime.h>
#include <cuda_fp16.h>
#include <math.h>
#include <stdint.h>

#define D_EMBED 2048
#define NHEAD   8
#define HDIM    256
#define BATCH   32
#define SEQ     256
#define ROWS    (BATCH*SEQ)   /* 8192 */
#define DFF     (4*D_EMBED)   /* 8192 */
#define BH      (BATCH*NHEAD) /* 256 */

// ---------------- scratch (device globals; no runtime allocation) -------------
__device__ __half g_hhi [ROWS*D_EMBED];
__device__ __half g_hlo [ROWS*D_EMBED];
__device__ __half g_qhi [ROWS*D_EMBED];
__device__ __half g_qlo [ROWS*D_EMBED];
__device__ __half g_khi [ROWS*D_EMBED];
__device__ __half g_klo [ROWS*D_EMBED];
__device__ float  g_v   [ROWS*D_EMBED];
__device__ __half g_vthi[ROWS*D_EMBED];
__device__ __half g_vtlo[ROWS*D_EMBED];
__device__ float  g_s   [BH*SEQ*SEQ];
__device__ __half g_shi [BH*SEQ*SEQ];
__device__ __half g_slo [BH*SEQ*SEQ];
__device__ __half g_aohi[ROWS*D_EMBED];
__device__ __half g_aolo[ROWS*D_EMBED];
__device__ float  g_x1  [ROWS*D_EMBED];
__device__ __half g_h2hi[ROWS*D_EMBED];
__device__ __half g_h2lo[ROWS*D_EMBED];
__device__ __half g_m1hi[(size_t)ROWS*DFF];
__device__ __half g_m1lo[(size_t)ROWS*DFF];
__device__ __half g_wqthi[D_EMBED*D_EMBED];
__device__ __half g_wqtlo[D_EMBED*D_EMBED];
__device__ __half g_wkthi[D_EMBED*D_EMBED];
__device__ __half g_wktlo[D_EMBED*D_EMBED];
__device__ __half g_wvthi[D_EMBED*D_EMBED];
__device__ __half g_wvtlo[D_EMBED*D_EMBED];
__device__ __half g_wothi[D_EMBED*D_EMBED];
__device__ __half g_wotlo[D_EMBED*D_EMBED];
__device__ __half g_w1thi[(size_t)D_EMBED*DFF];
__device__ __half g_w1tlo[(size_t)D_EMBED*DFF];
__device__ __half g_w2thi[(size_t)D_EMBED*DFF];
__device__ __half g_w2tlo[(size_t)D_EMBED*DFF];

// ---------------- helpers ------------------------------------------------------
__device__ __forceinline__ uint32_t smem_u32(const void* p) {
    uint32_t a;
    asm("{ .reg .u64 t; cvta.to.shared.u64 t, %1; cvt.u32.u64 %0, t; }" : "=r"(a) : "l"(p));
    return a;
}
__device__ __forceinline__ void cp16(uint32_t sdst, const void* gsrc) {
    asm volatile("cp.async.cg.shared.global [%0], [%1], 16;" :: "r"(sdst), "l"(gsrc));
}
#define CP_COMMIT() asm volatile("cp.async.commit_group;" ::: "memory")
#define CP_WAIT0()  asm volatile("cp.async.wait_group 0;" ::: "memory")

__device__ __forceinline__ void split16(float x, __half& hi, __half& lo) {
    hi = __float2half_rn(x);
    lo = __float2half_rn(x - __half2float(hi));
}
__device__ __forceinline__ void mma16(float* c, uint32_t a0, uint32_t a1,
                                      uint32_t a2, uint32_t a3,
                                      uint32_t b0, uint32_t b1) {
    asm volatile(
        "mma.sync.aligned.m16n8k16.row.col.f32.f16.f16.f32 "
        "{%0,%1,%2,%3}, {%4,%5,%6,%7}, {%8,%9}, {%0,%1,%2,%3};"
        : "+f"(c[0]), "+f"(c[1]), "+f"(c[2]), "+f"(c[3])
        : "r"(a0), "r"(a1), "r"(a2), "r"(a3), "r"(b0), "r"(b1));
}

// ---------------- layernorm (fp32 in -> fp16 hi/lo out) -----------------------
__global__ void __launch_bounds__(256) ln_kernel(const float* __restrict__ x,
                                                 const float* __restrict__ g,
                                                 const float* __restrict__ b,
                                                 __half* __restrict__ ohi,
                                                 __half* __restrict__ olo)
{
    __shared__ float red[256];
    const int row = blockIdx.x;
    const float* xr = x + (size_t)row * D_EMBED;
    const int tid = threadIdx.x;

    float v[8]; float s = 0.f;
#pragma unroll
    for (int i = 0; i < 8; i++) { v[i] = xr[tid + 256*i]; s += v[i]; }
    red[tid] = s; __syncthreads();
#pragma unroll
    for (int o = 128; o > 0; o >>= 1) { if (tid < o) red[tid] += red[tid+o]; __syncthreads(); }
    const float mean = red[0] * (1.0f / D_EMBED);
    __syncthreads();
    float qv = 0.f;
#pragma unroll
    for (int i = 0; i < 8; i++) { float d = v[i] - mean; qv += d*d; }
    red[tid] = qv; __syncthreads();
#pragma unroll
    for (int o = 128; o > 0; o >>= 1) { if (tid < o) red[tid] += red[tid+o]; __syncthreads(); }
    const float rstd = rsqrtf(red[0] * (1.0f / D_EMBED) + 1e-5f);

#pragma unroll
    for (int i = 0; i < 8; i++) {
        const int c = tid + 256*i;
        float o = (v[i] - mean) * rstd * g[c] + b[c];
        __half hi, lo; split16(o, hi, lo);
        ohi[(size_t)row * D_EMBED + c] = hi;
        olo[(size_t)row * D_EMBED + c] = lo;
    }
}

// ---------------- causal softmax (fp32 in -> fp16 hi/lo out) -------------------
__global__ void __launch_bounds__(256) softmax_kernel(const float* __restrict__ s,
                                                      __half* __restrict__ ohi,
                                                      __half* __restrict__ olo)
{
    __shared__ float red[256];
    const int row = blockIdx.x;
    const int t = row & (SEQ - 1);
    const float* sr = s + (size_t)row * SEQ;
    const int tid = threadIdx.x;

    const float val = (tid <= t) ? sr[tid] : -INFINITY;
    red[tid] = val; __syncthreads();
#pragma unroll
    for (int o = 128; o > 0; o >>= 1) { if (tid < o) red[tid] = fmaxf(red[tid], red[tid+o]); __syncthreads(); }
    const float mx = red[0];
    __syncthreads();
    const float e = (tid <= t) ? expf(val - mx) : 0.f;
    red[tid] = e; __syncthreads();
#pragma unroll
    for (int o = 128; o > 0; o >>= 1) { if (tid < o) red[tid] += red[tid+o]; __syncthreads(); }
    const float p = e / red[0];
    __half hi, lo; split16(p, hi, lo);
    ohi[(size_t)row * SEQ + tid] = hi;
    olo[(size_t)row * SEQ + tid] = lo;
}

// ---------------- transpose + split: fp32 [R x C] -> fp16 hi/lo [C x R] --------
__global__ void __launch_bounds__(256) transpose_split(
    const float* __restrict__ src, __half* __restrict__ dhi, __half* __restrict__ dlo,
    int R, int lds, int innerCnt, long sO, long sI, long dStride)
{
    __shared__ float t[32][33];
    const int z = blockIdx.z;
    const int zo = z / innerCnt, zi = z - zo * innerCnt;
    const float* s = src + (size_t)zo * sO + (size_t)zi * sI;
    __half* hi = dhi + (size_t)z * dStride;
    __half* lo = dlo + (size_t)z * dStride;
    const int c0 = blockIdx.x * 32, r0 = blockIdx.y * 32;
    const int x = threadIdx.x & 31, y = threadIdx.x >> 5;  // 32 x 8
#pragma unroll
    for (int i = 0; i < 32; i += 8)
        t[y + i][x] = s[(size_t)(r0 + y + i) * lds + c0 + x];
    __syncthreads();
#pragma unroll
    for (int i = 0; i < 32; i += 8) {
        float v = t[x][y + i];
        __half h, l; split16(v, h, l);
        size_t o = (size_t)(c0 + y + i) * R + r0 + x;
        hi[o] = h; lo[o] = l;
    }
}

// ---------------- fp16x3 mma.sync GEMM: 128x128 tile, BK=64 --------------------
// C[M][N] = alpha * A[M][K] * Bt[N][K]^T  (+ bias/gelu/res; fp32 and/or hi/lo out)
#define EP_BIAS   1
#define EP_GELU   2
#define EP_RES    4
#define EP_SPLIT  8
#define EP_STOREC 16

#define BK      64
#define ROWH    72                      /* halves per smem row (pad 64+8)  */
#define TILE_B  (128 * ROWH * 2)        /* 18432 bytes per tile            */
#define BUF_B   (4 * TILE_B)            /* Ahi,Alo,Bhi,Blo = 73728         */
#define SMEM_B  (2 * BUF_B)             /* double buffered = 147456        */

__device__ __forceinline__ void load_tile_async(const __half* __restrict__ G, int ld,
                                                int row0, int k0, uint32_t sbase, int tid)
{
#pragma unroll
    for (int it = 0; it < 4; it++) {
        const int c = tid + it * 256;         // 0..1023
        const int r = c >> 3, cb = c & 7;
        cp16(sbase + r * (ROWH * 2) + cb * 16,
             G + (size_t)(row0 + r) * ld + k0 + cb * 8);
    }
}

__global__ void __launch_bounds__(256, 1) gemm_hmma(
    const __half* __restrict__ Ahi, const __half* __restrict__ Alo,
    const __half* __restrict__ Bhi, const __half* __restrict__ Blo,
    const float* __restrict__ bias, const float* __restrict__ Rs,
    float* __restrict__ C, __half* __restrict__ Chi, __half* __restrict__ Clo,
    int K, int lda, int ldb, int ldc, int innerCnt,
    long aO, long aI, long bO, long bI, long cO, long cI,
    float alpha, int mode, int causal)
{
    extern __shared__ __align__(128) char sm[];

    const int bm = blockIdx.y * 128;
    const int bn = blockIdx.x * 128;
    if (causal && bn > bm) return;

    const int tid = threadIdx.x, wid = tid >> 5, lane = tid & 31;
    const int wm = (wid >> 2) * 64;     // 0 or 64
    const int wn = (wid & 3) * 32;      // 0,32,64,96
    const int lr = lane >> 2;           // 0..7
    const int lc2 = (lane & 3) * 2;     // 0,2,4,6

    const int z = blockIdx.z, zo = z / innerCnt, zi = z - zo * innerCnt;
    const __half* Ah = Ahi + (size_t)zo * aO + (size_t)zi * aI;
    const __half* Al = Alo + (size_t)zo * aO + (size_t)zi * aI;
    const __half* Bh = Bhi + (size_t)zo * bO + (size_t)zi * bI;
    const __half* Bl = Blo + (size_t)zo * bO + (size_t)zi * bI;
    const long coff = (size_t)zo * cO + (size_t)zi * cI;

    const uint32_t sb = smem_u32(sm);
    const int NB = K / BK;

    // prologue: block 0 -> buf 0
    load_tile_async(Ah, lda, bm, 0, sb + 0 * TILE_B, tid);
    load_tile_async(Al, lda, bm, 0, sb + 1 * TILE_B, tid);
    load_tile_async(Bh, ldb, bn, 0, sb + 2 * TILE_B, tid);
    load_tile_async(Bl, ldb, bn, 0, sb + 3 * TILE_B, tid);
    CP_COMMIT();
    CP_WAIT0();
    __syncthreads();

    float acc[4][4][4];
#pragma unroll
    for (int i = 0; i < 4; i++)
#pragma unroll
        for (int j = 0; j < 4; j++)
#pragma unroll
            for (int t = 0; t < 4; t++) acc[i][j][t] = 0.f;

    for (int blk = 0; blk < NB; blk++) {
        const int buf = blk & 1;
        if (blk + 1 < NB) {
            const uint32_t nb = sb + (buf ^ 1) * BUF_B;
            const int kk = (blk + 1) * BK;
            load_tile_async(Ah, lda, bm, kk, nb + 0 * TILE_B, tid);
            load_tile_async(Al, lda, bm, kk, nb + 1 * TILE_B, tid);
            load_tile_async(Bh, ldb, bn, kk, nb + 2 * TILE_B, tid);
            load_tile_async(Bl, ldb, bn, kk, nb + 3 * TILE_B, tid);
            CP_COMMIT();
        }

        const __half* ah = (const __half*)(sm + buf * BUF_B + 0 * TILE_B);
        const __half* al = (const __half*)(sm + buf * BUF_B + 1 * TILE_B);
        const __half* bh = (const __half*)(sm + buf * BUF_B + 2 * TILE_B);
        const __half* bl = (const __half*)(sm + buf * BUF_B + 3 * TILE_B);

#pragma unroll
        for (int ks = 0; ks < BK / 16; ks++) {
            const int koff = ks * 16;

            uint32_t aH[4][4], aL[4][4];
#pragma unroll
            for (int mt = 0; mt < 4; mt++) {
                const int base = (wm + mt * 16 + lr) * ROWH + koff + lc2;
                aH[mt][0] = *(const uint32_t*)&ah[base];
                aH[mt][1] = *(const uint32_t*)&ah[base + 8 * ROWH];
                aH[mt][2] = *(const uint32_t*)&ah[base + 8];
                aH[mt][3] = *(const uint32_t*)&ah[base + 8 * ROWH + 8];
                aL[mt][0] = *(const uint32_t*)&al[base];
                aL[mt][1] = *(const uint32_t*)&al[base + 8 * ROWH];
                aL[mt][2] = *(const uint32_t*)&al[base + 8];
                aL[mt][3] = *(const uint32_t*)&al[base + 8 * ROWH + 8];
            }
            uint32_t bH[4][2], bL[4][2];
#pragma unroll
            for (int nt = 0; nt < 4; nt++) {
                const int base = (wn + nt * 8 + lr) * ROWH + koff + lc2;
                bH[nt][0] = *(const uint32_t*)&bh[base];
                bH[nt][1] = *(const uint32_t*)&bh[base + 8];
                bL[nt][0] = *(const uint32_t*)&bl[base];
                bL[nt][1] = *(const uint32_t*)&bl[base + 8];
            }
#pragma unroll
            for (int mt = 0; mt < 4; mt++) {
#pragma unroll
                for (int nt = 0; nt < 4; nt++) {
                    mma16(acc[mt][nt], aH[mt][0], aH[mt][1], aH[mt][2], aH[mt][3],
                          bH[nt][0], bH[nt][1]);
                    mma16(acc[mt][nt], aL[mt][0], aL[mt][1], aL[mt][2], aL[mt][3],
                          bH[nt][0], bH[nt][1]);
                    mma16(acc[mt][nt], aH[mt][0], aH[mt][1], aH[mt][2], aH[mt][3],
                          bL[nt][0], bL[nt][1]);
                }
            }
        }

        if (blk + 1 < NB) CP_WAIT0();
        __syncthreads();
    }

    // ---- epilogue ----
#pragma unroll
    for (int mt = 0; mt < 4; mt++) {
#pragma unroll
        for (int half = 0; half < 2; half++) {
            const int rr = bm + wm + mt * 16 + lr + half * 8;
            float* crow = C + coff + (size_t)rr * ldc;
            const float* rrow = Rs + coff + (size_t)rr * ldc;
            __half* hrow = Chi + coff + (size_t)rr * ldc;
            __half* lrow = Clo + coff + (size_t)rr * ldc;
#pragma unroll
            for (int nt = 0; nt < 4; nt++) {
                const int col = bn + wn + nt * 8 + lc2;
                float o0 = alpha * acc[mt][nt][half * 2 + 0];
                float o1 = alpha * acc[mt][nt][half * 2 + 1];
                if (mode & EP_BIAS) {
                    const float2 bb = *(const float2*)(bias + col);
                    o0 += bb.x; o1 += bb.y;
                }
                if (mode & EP_GELU) {
                    o0 *= normcdff(o0);
                    o1 *= normcdff(o1);
                }
                if (mode & EP_RES) {
                    const float2 rv = *(const float2*)(rrow + col);
                    o0 += rv.x; o1 += rv.y;
                }
                if (mode & EP_STOREC)
                    *(float2*)(crow + col) = make_float2(o0, o1);
                if (mode & EP_SPLIT) {
                    __half h0, l0, h1, l1;
                    split16(o0, h0, l0);
                    split16(o1, h1, l1);
                    *(__half2*)(hrow + col) = __halves2half2(h0, h1);
                    *(__half2*)(lrow + col) = __halves2half2(l0, l1);
                }
            }
        }
    }
}

// ---------------- host-side launch helper -------------------------------------
static void gemm5(const __half* Ahi, const __half* Alo,
                  const __half* Bhi, const __half* Blo,
                  const float* bias, const float* res,
                  float* C, __half* Chi, __half* Clo,
                  int M, int N, int K, int lda, int ldb, int ldc, int mode,
                  float alpha = 1.f, int causal = 0, int batch = 1, int innerCnt = 1,
                  long aO = 0, long aI = 0, long bO = 0, long bI = 0,
                  long cO = 0, long cI = 0)
{
    static int attrDone = 0;
    if (!attrDone) {
        cudaFuncSetAttribute(gemm_hmma, cudaFuncAttributeMaxDynamicSharedMemorySize, SMEM_B);
        attrDone = 1;
    }
    dim3 grid(N / 128, M / 128, batch);
    gemm_hmma<<<grid, 256, SMEM_B>>>(Ahi, Alo, Bhi, Blo, bias, res, C, Chi, Clo,
                                     K, lda, ldb, ldc, innerCnt,
                                     aO, aI, bO, bI, cO, cI, alpha, mode, causal);
}

extern "C" void kernel_launch(void* const* d_in, const int* in_sizes, int n_in,
                              void* d_out, int out_size)
{
    const float* x    = (const float*)d_in[0];
    const float* ln1g = (const float*)d_in[1];
    const float* ln1b = (const float*)d_in[2];
    const float* wq   = (const float*)d_in[3];
    const float* bq   = (const float*)d_in[4];
    const float* wk   = (const float*)d_in[5];
    const float* bk   = (const float*)d_in[6];
    const float* wv   = (const float*)d_in[7];
    const float* bv   = (const float*)d_in[8];
    const float* wo   = (const float*)d_in[9];
    const float* bo   = (const float*)d_in[10];
    const float* ln2g = (const float*)d_in[11];
    const float* ln2b = (const float*)d_in[12];
    const float* w1   = (const float*)d_in[13];
    const float* b1   = (const float*)d_in[14];
    const float* w2   = (const float*)d_in[15];
    const float* b2   = (const float*)d_in[16];
    float* out = (float*)d_out;

    void* p;
#define GET(var, symn, T) cudaGetSymbolAddress(&p, symn); T* var = (T*)p
    GET(hhi, g_hhi, __half);  GET(hlo, g_hlo, __half);
    GET(qhi, g_qhi, __half);  GET(qlo, g_qlo, __half);
    GET(khi, g_khi, __half);  GET(klo, g_klo, __half);
    GET(v,   g_v,   float);
    GET(vthi,g_vthi,__half);  GET(vtlo,g_vtlo,__half);
    GET(s,   g_s,   float);
    GET(shi, g_shi, __half);  GET(slo, g_slo, __half);
    GET(aohi,g_aohi,__half);  GET(aolo,g_aolo,__half);
    GET(x1,  g_x1,  float);
    GET(h2hi,g_h2hi,__half);  GET(h2lo,g_h2lo,__half);
    GET(m1hi,g_m1hi,__half);  GET(m1lo,g_m1lo,__half);
    GET(wqthi,g_wqthi,__half); GET(wqtlo,g_wqtlo,__half);
    GET(wkthi,g_wkthi,__half); GET(wktlo,g_wktlo,__half);
    GET(wvthi,g_wvthi,__half); GET(wvtlo,g_wvtlo,__half);
    GET(wothi,g_wothi,__half); GET(wotlo,g_wotlo,__half);
    GET(w1thi,g_w1thi,__half); GET(w1tlo,g_w1tlo,__half);
    GET(w2thi,g_w2thi,__half); GET(w2tlo,g_w2tlo,__half);
#undef GET

    // weight transposes + splits: w[k][n] -> wt[n][k] fp16 hi/lo
    {
        dim3 blk(256);
        transpose_split<<<dim3(D_EMBED/32, D_EMBED/32, 1), blk>>>(wq, wqthi, wqtlo, D_EMBED, D_EMBED, 1, 0, 0, 0);
        transpose_split<<<dim3(D_EMBED/32, D_EMBED/32, 1), blk>>>(wk, wkthi, wktlo, D_EMBED, D_EMBED, 1, 0, 0, 0);
        transpose_split<<<dim3(D_EMBED/32, D_EMBED/32, 1), blk>>>(wv, wvthi, wvtlo, D_EMBED, D_EMBED, 1, 0, 0, 0);
        transpose_split<<<dim3(D_EMBED/32, D_EMBED/32, 1), blk>>>(wo, wothi, wotlo, D_EMBED, D_EMBED, 1, 0, 0, 0);
        transpose_split<<<dim3(DFF/32,     D_EMBED/32, 1), blk>>>(w1, w1thi, w1tlo, D_EMBED, DFF,     1, 0, 0, 0);
        transpose_split<<<dim3(D_EMBED/32, DFF/32,     1), blk>>>(w2, w2thi, w2tlo, DFF,     D_EMBED, 1, 0, 0, 0);
    }

    // 1. h = LN1(x) -> split
    ln_kernel<<<ROWS, 256>>>(x, ln1g, ln1b, hhi, hlo);

    // 2. Q, K (split out), V (fp32 out)
    gemm5(hhi, hlo, wqthi, wqtlo, bq, nullptr, nullptr, qhi, qlo,
          ROWS, D_EMBED, D_EMBED, D_EMBED, D_EMBED, D_EMBED, EP_BIAS | EP_SPLIT);
    gemm5(hhi, hlo, wkthi, wktlo, bk, nullptr, nullptr, khi, klo,
          ROWS, D_EMBED, D_EMBED, D_EMBED, D_EMBED, D_EMBED, EP_BIAS | EP_SPLIT);
    gemm5(hhi, hlo, wvthi, wvtlo, bv, nullptr, v, nullptr, nullptr,
          ROWS, D_EMBED, D_EMBED, D_EMBED, D_EMBED, D_EMBED, EP_BIAS | EP_STOREC);

    // 3. per-head transpose-split of V: vt[z][d][t]
    transpose_split<<<dim3(HDIM/32, SEQ/32, BH), 256>>>(
        v, vthi, vtlo, SEQ, D_EMBED, NHEAD,
        (long)SEQ * D_EMBED, (long)HDIM, (long)SEQ * HDIM);

    // 4. scores = (1/16) Q K^T  (batched over b,h; causal tile skip)
    gemm5(qhi, qlo, khi, klo, nullptr, nullptr, s, nullptr, nullptr,
          SEQ, SEQ, HDIM, D_EMBED, D_EMBED, SEQ, EP_STOREC,
          0.0625f, /*causal=*/1, BH, NHEAD,
          (long)SEQ * D_EMBED, (long)HDIM,
          (long)SEQ * D_EMBED, (long)HDIM,
          (long)NHEAD * SEQ * SEQ, (long)SEQ * SEQ);

    // 5. causal softmax -> split
    softmax_kernel<<<BH * SEQ, 256>>>(s, shi, slo);

    // 6. ao = att @ V  (split out)
    gemm5(shi, slo, vthi, vtlo, nullptr, nullptr, nullptr, aohi, aolo,
          SEQ, HDIM, SEQ, SEQ, SEQ, D_EMBED, EP_SPLIT,
          1.0f, 0, BH, NHEAD,
          (long)NHEAD * SEQ * SEQ, (long)SEQ * SEQ,
          (long)NHEAD * SEQ * HDIM, (long)SEQ * HDIM,
          (long)SEQ * D_EMBED, (long)HDIM);

    // 7. x1 = x + ao @ Wo + bo
    gemm5(aohi, aolo, wothi, wotlo, bo, x, x1, nullptr, nullptr,
          ROWS, D_EMBED, D_EMBED, D_EMBED, D_EMBED, D_EMBED,
          EP_BIAS | EP_RES | EP_STOREC);

    // 8. h2 = LN2(x1) -> split
    ln_kernel<<<ROWS, 256>>>(x1, ln2g, ln2b, h2hi, h2lo);

    // 9. m1 = gelu(h2 @ W1 + b1) -> split
    gemm5(h2hi, h2lo, w1thi, w1tlo, b1, nullptr, nullptr, m1hi, m1lo,
          ROWS, DFF, D_EMBED, D_EMBED, D_EMBED, DFF, EP_BIAS | EP_GELU | EP_SPLIT);

    // 10. out = x1 + m1 @ W2 + b2
    gemm5(m1hi, m1lo, w2thi, w2tlo, b2, x1, out, nullptr, nullptr,
          ROWS, D_EMBED, DFF, DFF, DFF, D_EMBED, EP_BIAS | EP_RES | EP_STOREC);
}